// round 2
// baseline (speedup 1.0000x reference)
#include <cuda_runtime.h>
#include <math.h>
#include <stdint.h>

#define HIDDEN 4096
#define INTER  16384
#define NTOK   8192
#define EPS    1e-5f

// Scratch (allocation-free: __device__ globals)
__device__ float g_res[(size_t)NTOK * HIDDEN];            // 128 MB
__device__ float g_ln[(size_t)NTOK * HIDDEN];             // 128 MB
__device__ float g_inter[(size_t)NTOK * INTER];           // 512 MB

__device__ __forceinline__ unsigned f2tf32u(float x) {
    unsigned r;
    asm("cvt.rna.tf32.f32 %0, %1;" : "=r"(r) : "f"(x));
    return r;
}

__device__ __forceinline__ void mma_tf32(float c[4], const unsigned a[4], const unsigned b[2]) {
    asm volatile(
        "mma.sync.aligned.m16n8k8.row.col.f32.tf32.tf32.f32 "
        "{%0,%1,%2,%3}, {%4,%5,%6,%7}, {%8,%9}, {%0,%1,%2,%3};\n"
        : "+f"(c[0]), "+f"(c[1]), "+f"(c[2]), "+f"(c[3])
        : "r"(a[0]), "r"(a[1]), "r"(a[2]), "r"(a[3]),
          "r"(b[0]), "r"(b[1]));
}

__device__ __forceinline__ float gelu_tanh(float x) {
    float x3 = x * x * x;
    float t = tanhf(0.7978845608028654f * (x + 0.044715f * x3));
    return 0.5f * x * (1.0f + t);
}

// ---------------------------------------------------------------------------
// Kernel 1: res = input + residual + bias; ln = LayerNorm(res)*gamma+beta
// One block per token row (4096 elems, 256 threads, 16 elems/thread)
// ---------------------------------------------------------------------------
__global__ __launch_bounds__(256)
void fused_add_ln(const float* __restrict__ inp,
                  const float* __restrict__ resd,
                  const float* __restrict__ bias,
                  const float* __restrict__ gamma,
                  const float* __restrict__ beta) {
    int row = blockIdx.x;
    int tid = threadIdx.x;
    const float4* ip = (const float4*)(inp  + (size_t)row * HIDDEN);
    const float4* rp = (const float4*)(resd + (size_t)row * HIDDEN);
    const float4* bp = (const float4*)bias;

    float4 v[4];
    float s = 0.f, ss = 0.f;
#pragma unroll
    for (int i = 0; i < 4; i++) {
        int idx = tid + i * 256;
        float4 a = ip[idx], b = rp[idx], c = bp[idx];
        float4 r;
        r.x = a.x + b.x + c.x;
        r.y = a.y + b.y + c.y;
        r.z = a.z + b.z + c.z;
        r.w = a.w + b.w + c.w;
        v[i] = r;
        s  += r.x + r.y + r.z + r.w;
        ss += r.x * r.x + r.y * r.y + r.z * r.z + r.w * r.w;
    }
    float4* ro = (float4*)(g_res + (size_t)row * HIDDEN);
#pragma unroll
    for (int i = 0; i < 4; i++) ro[tid + i * 256] = v[i];

    __shared__ float rs[256], rss[256];
    rs[tid] = s; rss[tid] = ss;
    __syncthreads();
    for (int o = 128; o > 0; o >>= 1) {
        if (tid < o) { rs[tid] += rs[tid + o]; rss[tid] += rss[tid + o]; }
        __syncthreads();
    }
    float mu   = rs[0] * (1.0f / HIDDEN);
    float var  = rss[0] * (1.0f / HIDDEN) - mu * mu;
    float rstd = rsqrtf(var + EPS);

    const float4* gp = (const float4*)gamma;
    const float4* btp = (const float4*)beta;
    float4* lo = (float4*)(g_ln + (size_t)row * HIDDEN);
#pragma unroll
    for (int i = 0; i < 4; i++) {
        int idx = tid + i * 256;
        float4 g = gp[idx], bt = btp[idx], r = v[i];
        float4 o;
        o.x = (r.x - mu) * rstd * g.x + bt.x;
        o.y = (r.y - mu) * rstd * g.y + bt.y;
        o.z = (r.z - mu) * rstd * g.z + bt.z;
        o.w = (r.w - mu) * rstd * g.w + bt.w;
        lo[idx] = o;
    }
}

// ---------------------------------------------------------------------------
// tf32 GEMM: C[M,N] = A[M,K] @ B[K,N] (+ epilogue)
// Block tile 128x128x32, 8 warps (4 in M x 2 in N), warp tile 32x64.
// EPI==0: A=g_ln,    epi = gelu(c + bias[n]) -> g_inter
// EPI==1: A=g_inter, epi = c + g_res[m,n] + bias[n] -> Cout
// ---------------------------------------------------------------------------
template <int EPI, int K, int N>
__global__ __launch_bounds__(256, 2)
void gemm_tf32(const float* __restrict__ B,
               const float* __restrict__ bias,
               float* __restrict__ Cout) {
    const float* __restrict__ A = (EPI == 0) ? g_ln : g_inter;

    __shared__ float sA[128 * 36];   // row stride 36 (pad 4)
    __shared__ float sB[32 * 132];   // row stride 132 (pad 4)

    int bm = blockIdx.y, bn = blockIdx.x;
    int tid = threadIdx.x;
    int warp = tid >> 5, lane = tid & 31;
    int wm = warp & 3;       // 0..3  -> 32-row slab
    int wn = warp >> 2;      // 0..1  -> 64-col slab
    int gID = lane >> 2;     // 0..7
    int tg = lane & 3;       // 0..3

    float acc[2][8][4];
#pragma unroll
    for (int mi = 0; mi < 2; mi++)
#pragma unroll
        for (int ni = 0; ni < 8; ni++)
#pragma unroll
            for (int j = 0; j < 4; j++) acc[mi][ni][j] = 0.f;

    for (int k0 = 0; k0 < K; k0 += 32) {
        // Load A tile: 128 x 32 floats (1024 float4)
#pragma unroll
        for (int i = 0; i < 4; i++) {
            int f = tid + i * 256;
            int r = f >> 3, c = (f & 7) << 2;
            float4 t = *(const float4*)(A + (size_t)(bm * 128 + r) * K + k0 + c);
            sA[r * 36 + c + 0] = __uint_as_float(f2tf32u(t.x));
            sA[r * 36 + c + 1] = __uint_as_float(f2tf32u(t.y));
            sA[r * 36 + c + 2] = __uint_as_float(f2tf32u(t.z));
            sA[r * 36 + c + 3] = __uint_as_float(f2tf32u(t.w));
        }
        // Load B tile: 32 x 128 floats
#pragma unroll
        for (int i = 0; i < 4; i++) {
            int f = tid + i * 256;
            int r = f >> 5, c = (f & 31) << 2;
            float4 t = *(const float4*)(B + (size_t)(k0 + r) * N + bn * 128 + c);
            sB[r * 132 + c + 0] = __uint_as_float(f2tf32u(t.x));
            sB[r * 132 + c + 1] = __uint_as_float(f2tf32u(t.y));
            sB[r * 132 + c + 2] = __uint_as_float(f2tf32u(t.z));
            sB[r * 132 + c + 3] = __uint_as_float(f2tf32u(t.w));
        }
        __syncthreads();

#pragma unroll
        for (int ks = 0; ks < 4; ks++) {
            int kk = ks * 8;
            unsigned a[2][4], b[8][2];
#pragma unroll
            for (int mi = 0; mi < 2; mi++) {
                int base = (wm * 32 + mi * 16 + gID) * 36 + kk + tg;
                a[mi][0] = __float_as_uint(sA[base]);
                a[mi][1] = __float_as_uint(sA[base + 8 * 36]);
                a[mi][2] = __float_as_uint(sA[base + 4]);
                a[mi][3] = __float_as_uint(sA[base + 8 * 36 + 4]);
            }
#pragma unroll
            for (int ni = 0; ni < 8; ni++) {
                int col = wn * 64 + ni * 8 + gID;
                b[ni][0] = __float_as_uint(sB[(kk + tg) * 132 + col]);
                b[ni][1] = __float_as_uint(sB[(kk + tg + 4) * 132 + col]);
            }
#pragma unroll
            for (int mi = 0; mi < 2; mi++)
#pragma unroll
                for (int ni = 0; ni < 8; ni++)
                    mma_tf32(acc[mi][ni], a[mi], b[ni]);
        }
        __syncthreads();
    }

    // Epilogue
#pragma unroll
    for (int mi = 0; mi < 2; mi++) {
#pragma unroll
        for (int ni = 0; ni < 8; ni++) {
            int row0 = bm * 128 + wm * 32 + mi * 16 + gID;
            int col0 = bn * 128 + wn * 64 + ni * 8 + tg * 2;
#pragma unroll
            for (int h = 0; h < 2; h++) {            // h=0 -> row0, h=1 -> row0+8
                int row = row0 + h * 8;
#pragma unroll
                for (int w = 0; w < 2; w++) {        // col0 / col0+1
                    int col = col0 + w;
                    float c = acc[mi][ni][h * 2 + w];
                    if (EPI == 0) {
                        float v = gelu_tanh(c + bias[col]);
                        g_inter[(size_t)row * INTER + col] = v;
                    } else {
                        float v = c + g_res[(size_t)row * HIDDEN + col] + bias[col];
                        Cout[(size_t)row * HIDDEN + col] = v;
                    }
                }
            }
        }
    }
}

// ---------------------------------------------------------------------------
extern "C" void kernel_launch(void* const* d_in, const int* in_sizes, int n_in,
                              void* d_out, int out_size) {
    const float* input    = (const float*)d_in[0];
    const float* residual = (const float*)d_in[1];
    // d_in[2] = residual_norm (unused by reference)
    const float* bias     = (const float*)d_in[3];
    const float* attn_nw  = (const float*)d_in[4];
    const float* attn_nb  = (const float*)d_in[5];
    const float* inter_w  = (const float*)d_in[6];
    const float* inter_b  = (const float*)d_in[7];
    const float* output_w = (const float*)d_in[8];
    const float* output_b = (const float*)d_in[9];
    float* out = (float*)d_out;

    fused_add_ln<<<NTOK, 256>>>(input, residual, bias, attn_nw, attn_nb);

    // GEMM1: [8192,4096] x [4096,16384] -> gelu -> g_inter
    {
        dim3 grid(INTER / 128, NTOK / 128);
        gemm_tf32<0, HIDDEN, INTER><<<grid, 256>>>(inter_w, inter_b, nullptr);
    }
    // GEMM2: [8192,16384] x [16384,4096] + res + output_b -> out
    {
        dim3 grid(HIDDEN / 128, NTOK / 128);
        gemm_tf32<1, INTER, HIDDEN><<<grid, 256>>>(output_w, output_b, out);
    }
}

// round 4
// speedup vs baseline: 1.0011x; 1.0011x over previous
#include <cuda_runtime.h>
#include <math.h>
#include <stdint.h>

#define HIDDEN 4096
#define INTER  16384
#define NTOK   8192
#define EPS    1e-5f

// Scratch (allocation-free: __device__ globals)
__device__ float g_res[(size_t)NTOK * HIDDEN];            // 128 MB
__device__ float g_ln[(size_t)NTOK * HIDDEN];             // 128 MB
__device__ float g_inter[(size_t)NTOK * INTER];           // 512 MB

__device__ __forceinline__ unsigned f2tf32u(float x) {
    unsigned r;
    asm("cvt.rna.tf32.f32 %0, %1;" : "=r"(r) : "f"(x));
    return r;
}

__device__ __forceinline__ void mma_tf32(float c[4], const unsigned a[4], const unsigned b[2]) {
    asm volatile(
        "mma.sync.aligned.m16n8k8.row.col.f32.tf32.tf32.f32 "
        "{%0,%1,%2,%3}, {%4,%5,%6,%7}, {%8,%9}, {%0,%1,%2,%3};\n"
        : "+f"(c[0]), "+f"(c[1]), "+f"(c[2]), "+f"(c[3])
        : "r"(a[0]), "r"(a[1]), "r"(a[2]), "r"(a[3]),
          "r"(b[0]), "r"(b[1]));
}

__device__ __forceinline__ float gelu_tanh(float x) {
    float x3 = x * x * x;
    float t = tanhf(0.7978845608028654f * (x + 0.044715f * x3));
    return 0.5f * x * (1.0f + t);
}

// ---------------------------------------------------------------------------
// Kernel 1: res = input + residual + bias; ln = LayerNorm(res)*gamma+beta
// One block per token row (4096 elems, 256 threads, 16 elems/thread)
// ---------------------------------------------------------------------------
__global__ __launch_bounds__(256)
void fused_add_ln(const float* __restrict__ inp,
                  const float* __restrict__ resd,
                  const float* __restrict__ bias,
                  const float* __restrict__ gamma,
                  const float* __restrict__ beta) {
    int row = blockIdx.x;
    int tid = threadIdx.x;
    const float4* ip = (const float4*)(inp  + (size_t)row * HIDDEN);
    const float4* rp = (const float4*)(resd + (size_t)row * HIDDEN);
    const float4* bp = (const float4*)bias;

    float4 v[4];
    float s = 0.f, ss = 0.f;
#pragma unroll
    for (int i = 0; i < 4; i++) {
        int idx = tid + i * 256;
        float4 a = ip[idx], b = rp[idx], c = bp[idx];
        float4 r;
        r.x = a.x + b.x + c.x;
        r.y = a.y + b.y + c.y;
        r.z = a.z + b.z + c.z;
        r.w = a.w + b.w + c.w;
        v[i] = r;
        s  += r.x + r.y + r.z + r.w;
        ss += r.x * r.x + r.y * r.y + r.z * r.z + r.w * r.w;
    }
    float4* ro = (float4*)(g_res + (size_t)row * HIDDEN);
#pragma unroll
    for (int i = 0; i < 4; i++) ro[tid + i * 256] = v[i];

    __shared__ float rs[256], rss[256];
    rs[tid] = s; rss[tid] = ss;
    __syncthreads();
    for (int o = 128; o > 0; o >>= 1) {
        if (tid < o) { rs[tid] += rs[tid + o]; rss[tid] += rss[tid + o]; }
        __syncthreads();
    }
    float mu   = rs[0] * (1.0f / HIDDEN);
    float var  = rss[0] * (1.0f / HIDDEN) - mu * mu;
    float rstd = rsqrtf(var + EPS);

    const float4* gp = (const float4*)gamma;
    const float4* btp = (const float4*)beta;
    float4* lo = (float4*)(g_ln + (size_t)row * HIDDEN);
#pragma unroll
    for (int i = 0; i < 4; i++) {
        int idx = tid + i * 256;
        float4 g = gp[idx], bt = btp[idx], r = v[i];
        float4 o;
        o.x = (r.x - mu) * rstd * g.x + bt.x;
        o.y = (r.y - mu) * rstd * g.y + bt.y;
        o.z = (r.z - mu) * rstd * g.z + bt.z;
        o.w = (r.w - mu) * rstd * g.w + bt.w;
        lo[idx] = o;
    }
}

// ---------------------------------------------------------------------------
// tf32 GEMM: C[M,N] = A[M,K] @ B[K,N] (+ epilogue)
// Block tile 128x128x32, 8 warps (4 in M x 2 in N), warp tile 32x64.
// EPI==0: A=g_ln,    epi = gelu(c + bias[n]) -> g_inter
// EPI==1: A=g_inter, epi = c + g_res[m,n] + bias[n] -> Cout
// ---------------------------------------------------------------------------
template <int EPI, int K, int N>
__global__ __launch_bounds__(256, 2)
void gemm_tf32(const float* __restrict__ B,
               const float* __restrict__ bias,
               float* __restrict__ Cout) {
    const float* __restrict__ A = (EPI == 0) ? g_ln : g_inter;

    __shared__ float sA[128 * 36];   // row stride 36 (pad 4)
    __shared__ float sB[32 * 132];   // row stride 132 (pad 4)

    int bm = blockIdx.y, bn = blockIdx.x;
    int tid = threadIdx.x;
    int warp = tid >> 5, lane = tid & 31;
    int wm = warp & 3;       // 0..3  -> 32-row slab
    int wn = warp >> 2;      // 0..1  -> 64-col slab
    int gID = lane >> 2;     // 0..7
    int tg = lane & 3;       // 0..3

    float acc[2][8][4];
#pragma unroll
    for (int mi = 0; mi < 2; mi++)
#pragma unroll
        for (int ni = 0; ni < 8; ni++)
#pragma unroll
            for (int j = 0; j < 4; j++) acc[mi][ni][j] = 0.f;

    for (int k0 = 0; k0 < K; k0 += 32) {
        // Load A tile: 128 x 32 floats (1024 float4)
#pragma unroll
        for (int i = 0; i < 4; i++) {
            int f = tid + i * 256;
            int r = f >> 3, c = (f & 7) << 2;
            float4 t = *(const float4*)(A + (size_t)(bm * 128 + r) * K + k0 + c);
            sA[r * 36 + c + 0] = __uint_as_float(f2tf32u(t.x));
            sA[r * 36 + c + 1] = __uint_as_float(f2tf32u(t.y));
            sA[r * 36 + c + 2] = __uint_as_float(f2tf32u(t.z));
            sA[r * 36 + c + 3] = __uint_as_float(f2tf32u(t.w));
        }
        // Load B tile: 32 x 128 floats
#pragma unroll
        for (int i = 0; i < 4; i++) {
            int f = tid + i * 256;
            int r = f >> 5, c = (f & 31) << 2;
            float4 t = *(const float4*)(B + (size_t)(k0 + r) * N + bn * 128 + c);
            sB[r * 132 + c + 0] = __uint_as_float(f2tf32u(t.x));
            sB[r * 132 + c + 1] = __uint_as_float(f2tf32u(t.y));
            sB[r * 132 + c + 2] = __uint_as_float(f2tf32u(t.z));
            sB[r * 132 + c + 3] = __uint_as_float(f2tf32u(t.w));
        }
        __syncthreads();

#pragma unroll
        for (int ks = 0; ks < 4; ks++) {
            int kk = ks * 8;
            unsigned a[2][4], b[8][2];
#pragma unroll
            for (int mi = 0; mi < 2; mi++) {
                int base = (wm * 32 + mi * 16 + gID) * 36 + kk + tg;
                a[mi][0] = __float_as_uint(sA[base]);
                a[mi][1] = __float_as_uint(sA[base + 8 * 36]);
                a[mi][2] = __float_as_uint(sA[base + 4]);
                a[mi][3] = __float_as_uint(sA[base + 8 * 36 + 4]);
            }
#pragma unroll
            for (int ni = 0; ni < 8; ni++) {
                int col = wn * 64 + ni * 8 + gID;
                b[ni][0] = __float_as_uint(sB[(kk + tg) * 132 + col]);
                b[ni][1] = __float_as_uint(sB[(kk + tg + 4) * 132 + col]);
            }
#pragma unroll
            for (int mi = 0; mi < 2; mi++)
#pragma unroll
                for (int ni = 0; ni < 8; ni++)
                    mma_tf32(acc[mi][ni], a[mi], b[ni]);
        }
        __syncthreads();
    }

    // Epilogue
#pragma unroll
    for (int mi = 0; mi < 2; mi++) {
#pragma unroll
        for (int ni = 0; ni < 8; ni++) {
            int row0 = bm * 128 + wm * 32 + mi * 16 + gID;
            int col0 = bn * 128 + wn * 64 + ni * 8 + tg * 2;
#pragma unroll
            for (int h = 0; h < 2; h++) {            // h=0 -> row0, h=1 -> row0+8
                int row = row0 + h * 8;
#pragma unroll
                for (int w = 0; w < 2; w++) {        // col0 / col0+1
                    int col = col0 + w;
                    float c = acc[mi][ni][h * 2 + w];
                    if (EPI == 0) {
                        float v = gelu_tanh(c + bias[col]);
                        g_inter[(size_t)row * INTER + col] = v;
                    } else {
                        float v = c + g_res[(size_t)row * HIDDEN + col] + bias[col];
                        Cout[(size_t)row * HIDDEN + col] = v;
                    }
                }
            }
        }
    }
}

// ---------------------------------------------------------------------------
extern "C" void kernel_launch(void* const* d_in, const int* in_sizes, int n_in,
                              void* d_out, int out_size) {
    const float* input    = (const float*)d_in[0];
    const float* residual = (const float*)d_in[1];
    // d_in[2] = residual_norm (unused by reference)
    const float* bias     = (const float*)d_in[3];
    const float* attn_nw  = (const float*)d_in[4];
    const float* attn_nb  = (const float*)d_in[5];
    const float* inter_w  = (const float*)d_in[6];
    const float* inter_b  = (const float*)d_in[7];
    const float* output_w = (const float*)d_in[8];
    const float* output_b = (const float*)d_in[9];
    float* out = (float*)d_out;

    fused_add_ln<<<NTOK, 256>>>(input, residual, bias, attn_nw, attn_nb);

    // GEMM1: [8192,4096] x [4096,16384] -> gelu -> g_inter
    {
        dim3 grid(INTER / 128, NTOK / 128);
        gemm_tf32<0, HIDDEN, INTER><<<grid, 256>>>(inter_w, inter_b, nullptr);
    }
    // GEMM2: [8192,16384] x [16384,4096] + res + output_b -> out
    {
        dim3 grid(HIDDEN / 128, NTOK / 128);
        gemm_tf32<1, INTER, HIDDEN><<<grid, 256>>>(output_w, output_b, out);
    }
}